// round 1
// baseline (speedup 1.0000x reference)
#include <cuda_runtime.h>

#define HDIM 4
#define TSTEPS 7

__device__ __forceinline__ float fast_tanh(float x) {
    // tanh(x) = sign(x) * (1 - 2/(exp(2|x|)+1)); saturates correctly (exp->inf => 1)
    float e = __expf(2.0f * fabsf(x));
    float t = 1.0f - __fdividef(2.0f, e + 1.0f);
    return copysignf(t, x);
}

__global__ __launch_bounds__(256, 1)
void rec_policy_kernel(const float* __restrict__ x,
                       const float* __restrict__ Wih_up, const float* __restrict__ Whh_up,
                       const float* __restrict__ bih_up, const float* __restrict__ bhh_up,
                       const float* __restrict__ W1,     const float* __restrict__ b1,
                       const float* __restrict__ W2,     const float* __restrict__ b2,
                       const float* __restrict__ Wih_dn, const float* __restrict__ Whh_dn,
                       const float* __restrict__ bih_dn, const float* __restrict__ bhh_dn,
                       const float* __restrict__ Wo,     const float* __restrict__ bo,
                       float* __restrict__ out, int B)
{
    int row = blockIdx.x * blockDim.x + threadIdx.x;
    if (row >= B) return;

    // ---- weights into registers (uniform addresses -> L1 broadcast) ----
    float wiu[HDIM][2], whu[HDIM][HDIM], bu[HDIM];
    float w1[HDIM][8], c1[HDIM], w2[HDIM][HDIM], c2[HDIM];
    float wid[HDIM][HDIM], whd[HDIM][HDIM], bd[HDIM];
    float wo[5], bo0 = bo[0];

    #pragma unroll
    for (int i = 0; i < HDIM; i++) {
        wiu[i][0] = Wih_up[i*2+0];
        wiu[i][1] = Wih_up[i*2+1];
        bu[i] = bih_up[i] + bhh_up[i];
        bd[i] = bih_dn[i] + bhh_dn[i];
        c1[i] = b1[i];
        c2[i] = b2[i];
        #pragma unroll
        for (int k = 0; k < HDIM; k++) {
            whu[i][k] = Whh_up[i*HDIM+k];
            w2 [i][k] = W2    [i*HDIM+k];
            wid[i][k] = Wih_dn[i*HDIM+k];
            whd[i][k] = Whh_dn[i*HDIM+k];
        }
        #pragma unroll
        for (int k = 0; k < 8; k++) w1[i][k] = W1[i*8+k];
    }
    #pragma unroll
    for (int k = 0; k < 5; k++) wo[k] = Wo[k];

    // ---- load this row: 18 floats, 8B-aligned -> 9x float2 ----
    float xr[18];
    const float2* xp = reinterpret_cast<const float2*>(x + (size_t)row * 18);
    #pragma unroll
    for (int k = 0; k < 9; k++) {
        float2 v = xp[k];
        xr[2*k]   = v.x;
        xr[2*k+1] = v.y;
    }
    const float* obs = xr;       // x[:, 0:4]
    const float* jj  = xr + 4;   // x[:, 4:11]
    const float* jjd = xr + 11;  // x[:, 11:18]

    // ---- up scan (time reversed: step s uses original index 6-s) ----
    float h[HDIM] = {0.f, 0.f, 0.f, 0.f};
    float hup[TSTEPS][HDIM];
    #pragma unroll
    for (int s = 0; s < TSTEPS; s++) {
        const int ti = TSTEPS - 1 - s;
        float pre[HDIM];
        #pragma unroll
        for (int i = 0; i < HDIM; i++) {
            float p = bu[i];
            p += wiu[i][0] * jj[ti];
            p += wiu[i][1] * jjd[ti];
            #pragma unroll
            for (int k = 0; k < HDIM; k++) p += whu[i][k] * h[k];
            pre[i] = p;
        }
        #pragma unroll
        for (int i = 0; i < HDIM; i++) {
            h[i] = fast_tanh(pre[i]);
            hup[ti][i] = h[i];   // h_up (un-reversed order)
        }
    }
    // h now == h_last

    // ---- h0 = tanh(tanh([obs, h_last] @ W1^T + b1) @ W2^T + b2) ----
    float z[8];
    #pragma unroll
    for (int k = 0; k < 4; k++) { z[k] = obs[k]; z[4+k] = h[k]; }
    float h0[HDIM];
    #pragma unroll
    for (int i = 0; i < HDIM; i++) {
        float p = c1[i];
        #pragma unroll
        for (int k = 0; k < 8; k++) p += w1[i][k] * z[k];
        h0[i] = fast_tanh(p);
    }
    #pragma unroll
    for (int i = 0; i < HDIM; i++) {
        float p = c2[i];
        #pragma unroll
        for (int k = 0; k < HDIM; k++) p += w2[i][k] * h0[k];
        h[i] = fast_tanh(p);
    }

    // ---- down scan ----
    float acts[TSTEPS];
    #pragma unroll
    for (int t = 0; t < TSTEPS; t++) {
        float a = bo0 + wo[4] * jj[t];
        #pragma unroll
        for (int k = 0; k < HDIM; k++) a += wo[k] * h[k];
        acts[t] = a;

        float hn[HDIM];
        #pragma unroll
        for (int i = 0; i < HDIM; i++) {
            float p = bd[i];
            #pragma unroll
            for (int k = 0; k < HDIM; k++) {
                p += wid[i][k] * hup[t][k];
                p += whd[i][k] * h[k];
            }
            hn[i] = fast_tanh(p);
        }
        #pragma unroll
        for (int i = 0; i < HDIM; i++) h[i] = hn[i];
    }

    // ---- store 7 outputs ----
    float* op = out + (size_t)row * TSTEPS;
    #pragma unroll
    for (int t = 0; t < TSTEPS; t++) op[t] = acts[t];
}

extern "C" void kernel_launch(void* const* d_in, const int* in_sizes, int n_in,
                              void* d_out, int out_size)
{
    const float* x      = (const float*)d_in[0];
    const float* Wih_up = (const float*)d_in[1];
    const float* Whh_up = (const float*)d_in[2];
    const float* bih_up = (const float*)d_in[3];
    const float* bhh_up = (const float*)d_in[4];
    const float* W1     = (const float*)d_in[5];
    const float* b1     = (const float*)d_in[6];
    const float* W2     = (const float*)d_in[7];
    const float* b2     = (const float*)d_in[8];
    const float* Wih_dn = (const float*)d_in[9];
    const float* Whh_dn = (const float*)d_in[10];
    const float* bih_dn = (const float*)d_in[11];
    const float* bhh_dn = (const float*)d_in[12];
    const float* Wo     = (const float*)d_in[13];
    const float* bo     = (const float*)d_in[14];
    float* out = (float*)d_out;

    int B = in_sizes[0] / 18;
    int threads = 256;
    int blocks = (B + threads - 1) / threads;
    rec_policy_kernel<<<blocks, threads>>>(x, Wih_up, Whh_up, bih_up, bhh_up,
                                           W1, b1, W2, b2,
                                           Wih_dn, Whh_dn, bih_dn, bhh_dn,
                                           Wo, bo, out, B);
}

// round 2
// speedup vs baseline: 2.0480x; 2.0480x over previous
#include <cuda_runtime.h>

#define HDIM 4
#define TSTEPS 7

// tanh(x) where the input has been pre-scaled by 2*log2(e) (folded into weights):
// given p = 2*log2(e)*x, tanh(x) = 1 - 2/(2^p + 1).
// Sign-correct for all x: p -> -inf => 2^p -> 0 => -1; p -> +inf => 2^p -> inf => +1.
__device__ __forceinline__ float tanh_pre(float p) {
    float e, r;
    asm("ex2.approx.f32 %0, %1;" : "=f"(e) : "f"(p));
    float d = e + 1.0f;
    asm("rcp.approx.f32 %0, %1;" : "=f"(r) : "f"(d));
    return fmaf(-2.0f, r, 1.0f);
}

__global__ __launch_bounds__(256, 2)
void rec_policy_kernel(const float* __restrict__ x,
                       const float* __restrict__ Wih_up, const float* __restrict__ Whh_up,
                       const float* __restrict__ bih_up, const float* __restrict__ bhh_up,
                       const float* __restrict__ W1,     const float* __restrict__ b1,
                       const float* __restrict__ W2,     const float* __restrict__ b2,
                       const float* __restrict__ Wih_dn, const float* __restrict__ Whh_dn,
                       const float* __restrict__ bih_dn, const float* __restrict__ bhh_dn,
                       const float* __restrict__ Wo,     const float* __restrict__ bo,
                       float* __restrict__ out, int B)
{
    // h_up history spilled to shared, transposed: [t*4+k][lane] -> stride-1, no conflicts
    __shared__ float hup_s[TSTEPS * HDIM][256];

    int tid = threadIdx.x;
    int row = blockIdx.x * blockDim.x + tid;
    if (row >= B) return;

    const float SC = 2.885390081777927f; // 2 * log2(e), folded into all pre-tanh weights

    // ---- weights into registers (uniform addresses -> broadcast) ----
    float wiu[HDIM][2], whu[HDIM][HDIM], bu[HDIM];
    float w1[HDIM][8], c1[HDIM], w2[HDIM][HDIM], c2[HDIM];
    float wid[HDIM][HDIM], whd[HDIM][HDIM], bd[HDIM];
    float wo[5], bo0 = bo[0];

    #pragma unroll
    for (int i = 0; i < HDIM; i++) {
        wiu[i][0] = SC * Wih_up[i*2+0];
        wiu[i][1] = SC * Wih_up[i*2+1];
        bu[i] = SC * (bih_up[i] + bhh_up[i]);
        bd[i] = SC * (bih_dn[i] + bhh_dn[i]);
        c1[i] = SC * b1[i];
        c2[i] = SC * b2[i];
        #pragma unroll
        for (int k = 0; k < HDIM; k++) {
            whu[i][k] = SC * Whh_up[i*HDIM+k];
            w2 [i][k] = SC * W2    [i*HDIM+k];
            wid[i][k] = SC * Wih_dn[i*HDIM+k];
            whd[i][k] = SC * Whh_dn[i*HDIM+k];
        }
        #pragma unroll
        for (int k = 0; k < 8; k++) w1[i][k] = SC * W1[i*8+k];
    }
    #pragma unroll
    for (int k = 0; k < 5; k++) wo[k] = Wo[k];   // output layer is linear: NOT scaled

    // ---- load this row: 18 floats, 8B-aligned -> 9x float2 ----
    float xr[18];
    const float2* xp = reinterpret_cast<const float2*>(x + (size_t)row * 18);
    #pragma unroll
    for (int k = 0; k < 9; k++) {
        float2 v = xp[k];
        xr[2*k]   = v.x;
        xr[2*k+1] = v.y;
    }
    const float* obs = xr;       // x[:, 0:4]
    const float* jj  = xr + 4;   // x[:, 4:11]
    const float* jjd = xr + 11;  // x[:, 11:18]

    // ---- up scan (time reversed: step s uses original index 6-s) ----
    float h[HDIM] = {0.f, 0.f, 0.f, 0.f};
    #pragma unroll
    for (int s = 0; s < TSTEPS; s++) {
        const int ti = TSTEPS - 1 - s;
        float pre[HDIM];
        #pragma unroll
        for (int i = 0; i < HDIM; i++) {
            float p = bu[i];
            p = fmaf(wiu[i][0], jj[ti],  p);
            p = fmaf(wiu[i][1], jjd[ti], p);
            #pragma unroll
            for (int k = 0; k < HDIM; k++) p = fmaf(whu[i][k], h[k], p);
            pre[i] = p;
        }
        #pragma unroll
        for (int i = 0; i < HDIM; i++) {
            h[i] = tanh_pre(pre[i]);
            hup_s[ti*HDIM + i][tid] = h[i];
        }
    }
    // h now == h_last

    // ---- h0 = tanh(tanh([obs, h_last] @ W1^T + b1) @ W2^T + b2) ----
    float z[8];
    #pragma unroll
    for (int k = 0; k < 4; k++) { z[k] = obs[k]; z[4+k] = h[k]; }
    float h0[HDIM];
    #pragma unroll
    for (int i = 0; i < HDIM; i++) {
        float p = c1[i];
        #pragma unroll
        for (int k = 0; k < 8; k++) p = fmaf(w1[i][k], z[k], p);
        h0[i] = tanh_pre(p);
    }
    #pragma unroll
    for (int i = 0; i < HDIM; i++) {
        float p = c2[i];
        #pragma unroll
        for (int k = 0; k < HDIM; k++) p = fmaf(w2[i][k], h0[k], p);
        h[i] = tanh_pre(p);
    }

    // ---- down scan ----
    float acts[TSTEPS];
    #pragma unroll
    for (int t = 0; t < TSTEPS; t++) {
        float a = fmaf(wo[4], jj[t], bo0);
        #pragma unroll
        for (int k = 0; k < HDIM; k++) a = fmaf(wo[k], h[k], a);
        acts[t] = a;

        float hn[HDIM];
        #pragma unroll
        for (int i = 0; i < HDIM; i++) {
            float p = bd[i];
            #pragma unroll
            for (int k = 0; k < HDIM; k++) {
                p = fmaf(wid[i][k], hup_s[t*HDIM + k][tid], p);
                p = fmaf(whd[i][k], h[k], p);
            }
            hn[i] = tanh_pre(p);
        }
        #pragma unroll
        for (int i = 0; i < HDIM; i++) h[i] = hn[i];
    }

    // ---- store 7 outputs ----
    float* op = out + (size_t)row * TSTEPS;
    #pragma unroll
    for (int t = 0; t < TSTEPS; t++) op[t] = acts[t];
}

extern "C" void kernel_launch(void* const* d_in, const int* in_sizes, int n_in,
                              void* d_out, int out_size)
{
    const float* x      = (const float*)d_in[0];
    const float* Wih_up = (const float*)d_in[1];
    const float* Whh_up = (const float*)d_in[2];
    const float* bih_up = (const float*)d_in[3];
    const float* bhh_up = (const float*)d_in[4];
    const float* W1     = (const float*)d_in[5];
    const float* b1     = (const float*)d_in[6];
    const float* W2     = (const float*)d_in[7];
    const float* b2     = (const float*)d_in[8];
    const float* Wih_dn = (const float*)d_in[9];
    const float* Whh_dn = (const float*)d_in[10];
    const float* bih_dn = (const float*)d_in[11];
    const float* bhh_dn = (const float*)d_in[12];
    const float* Wo     = (const float*)d_in[13];
    const float* bo     = (const float*)d_in[14];
    float* out = (float*)d_out;

    int B = in_sizes[0] / 18;
    int threads = 256;
    int blocks = (B + threads - 1) / threads;
    rec_policy_kernel<<<blocks, threads>>>(x, Wih_up, Whh_up, bih_up, bhh_up,
                                           W1, b1, W2, b2,
                                           Wih_dn, Whh_dn, bih_dn, bhh_dn,
                                           Wo, bo, out, B);
}

// round 3
// speedup vs baseline: 2.8355x; 1.3846x over previous
#include <cuda_runtime.h>

#define HDIM 4
#define TSTEPS 7

// Single-instruction HW tanh (MUFU.TANH, sm_75+). Max abs err ~5e-4 — well inside
// the 1e-3 rel-err budget for this contractive network.
__device__ __forceinline__ float htanh(float x) {
    float r;
    asm("tanh.approx.f32 %0, %1;" : "=f"(r) : "f"(x));
    return r;
}

__global__ __launch_bounds__(256, 2)
void rec_policy_kernel(const float* __restrict__ x,
                       const float* __restrict__ Wih_up, const float* __restrict__ Whh_up,
                       const float* __restrict__ bih_up, const float* __restrict__ bhh_up,
                       const float* __restrict__ W1,     const float* __restrict__ b1,
                       const float* __restrict__ W2,     const float* __restrict__ b2,
                       const float* __restrict__ Wih_dn, const float* __restrict__ Whh_dn,
                       const float* __restrict__ bih_dn, const float* __restrict__ bhh_dn,
                       const float* __restrict__ Wo,     const float* __restrict__ bo,
                       float* __restrict__ out, int B)
{
    // h_up history in shared, transposed: [t*4+k][lane] -> stride-1, conflict-free
    __shared__ float hup_s[TSTEPS * HDIM][256];

    int tid = threadIdx.x;
    int row = blockIdx.x * blockDim.x + tid;
    if (row >= B) return;

    // ---- weights into registers (uniform addresses -> broadcast) ----
    float wiu[HDIM][2], whu[HDIM][HDIM], bu[HDIM];
    float w1[HDIM][8], c1[HDIM], w2[HDIM][HDIM], c2[HDIM];
    float wid[HDIM][HDIM], whd[HDIM][HDIM], bd[HDIM];
    float wo[5], bo0 = bo[0];

    #pragma unroll
    for (int i = 0; i < HDIM; i++) {
        wiu[i][0] = Wih_up[i*2+0];
        wiu[i][1] = Wih_up[i*2+1];
        bu[i] = bih_up[i] + bhh_up[i];
        bd[i] = bih_dn[i] + bhh_dn[i];
        c1[i] = b1[i];
        c2[i] = b2[i];
        #pragma unroll
        for (int k = 0; k < HDIM; k++) {
            whu[i][k] = Whh_up[i*HDIM+k];
            w2 [i][k] = W2    [i*HDIM+k];
            wid[i][k] = Wih_dn[i*HDIM+k];
            whd[i][k] = Whh_dn[i*HDIM+k];
        }
        #pragma unroll
        for (int k = 0; k < 8; k++) w1[i][k] = W1[i*8+k];
    }
    #pragma unroll
    for (int k = 0; k < 5; k++) wo[k] = Wo[k];

    // ---- load this row: 18 floats, 8B-aligned -> 9x float2 ----
    float xr[18];
    const float2* xp = reinterpret_cast<const float2*>(x + (size_t)row * 18);
    #pragma unroll
    for (int k = 0; k < 9; k++) {
        float2 v = xp[k];
        xr[2*k]   = v.x;
        xr[2*k+1] = v.y;
    }
    const float* obs = xr;       // x[:, 0:4]
    const float* jj  = xr + 4;   // x[:, 4:11]
    const float* jjd = xr + 11;  // x[:, 11:18]

    // ---- up scan (time reversed: step s uses original index 6-s) ----
    float h[HDIM] = {0.f, 0.f, 0.f, 0.f};
    #pragma unroll
    for (int s = 0; s < TSTEPS; s++) {
        const int ti = TSTEPS - 1 - s;
        float pre[HDIM];
        #pragma unroll
        for (int i = 0; i < HDIM; i++) {
            float p = bu[i];
            p = fmaf(wiu[i][0], jj[ti],  p);
            p = fmaf(wiu[i][1], jjd[ti], p);
            #pragma unroll
            for (int k = 0; k < HDIM; k++) p = fmaf(whu[i][k], h[k], p);
            pre[i] = p;
        }
        #pragma unroll
        for (int i = 0; i < HDIM; i++) {
            h[i] = htanh(pre[i]);
            hup_s[ti*HDIM + i][tid] = h[i];
        }
    }
    // h now == h_last

    // ---- h0 = tanh(tanh([obs, h_last] @ W1^T + b1) @ W2^T + b2) ----
    float z[8];
    #pragma unroll
    for (int k = 0; k < 4; k++) { z[k] = obs[k]; z[4+k] = h[k]; }
    float h0[HDIM];
    #pragma unroll
    for (int i = 0; i < HDIM; i++) {
        float p = c1[i];
        #pragma unroll
        for (int k = 0; k < 8; k++) p = fmaf(w1[i][k], z[k], p);
        h0[i] = htanh(p);
    }
    #pragma unroll
    for (int i = 0; i < HDIM; i++) {
        float p = c2[i];
        #pragma unroll
        for (int k = 0; k < HDIM; k++) p = fmaf(w2[i][k], h0[k], p);
        h[i] = htanh(p);
    }

    // ---- down scan ----
    float acts[TSTEPS];
    #pragma unroll
    for (int t = 0; t < TSTEPS; t++) {
        float a = fmaf(wo[4], jj[t], bo0);
        #pragma unroll
        for (int k = 0; k < HDIM; k++) a = fmaf(wo[k], h[k], a);
        acts[t] = a;

        float hn[HDIM];
        #pragma unroll
        for (int i = 0; i < HDIM; i++) {
            float p = bd[i];
            #pragma unroll
            for (int k = 0; k < HDIM; k++) {
                p = fmaf(wid[i][k], hup_s[t*HDIM + k][tid], p);
                p = fmaf(whd[i][k], h[k], p);
            }
            hn[i] = htanh(p);
        }
        #pragma unroll
        for (int i = 0; i < HDIM; i++) h[i] = hn[i];
    }

    // ---- store 7 outputs ----
    float* op = out + (size_t)row * TSTEPS;
    #pragma unroll
    for (int t = 0; t < TSTEPS; t++) op[t] = acts[t];
}

extern "C" void kernel_launch(void* const* d_in, const int* in_sizes, int n_in,
                              void* d_out, int out_size)
{
    const float* x      = (const float*)d_in[0];
    const float* Wih_up = (const float*)d_in[1];
    const float* Whh_up = (const float*)d_in[2];
    const float* bih_up = (const float*)d_in[3];
    const float* bhh_up = (const float*)d_in[4];
    const float* W1     = (const float*)d_in[5];
    const float* b1     = (const float*)d_in[6];
    const float* W2     = (const float*)d_in[7];
    const float* b2     = (const float*)d_in[8];
    const float* Wih_dn = (const float*)d_in[9];
    const float* Whh_dn = (const float*)d_in[10];
    const float* bih_dn = (const float*)d_in[11];
    const float* bhh_dn = (const float*)d_in[12];
    const float* Wo     = (const float*)d_in[13];
    const float* bo     = (const float*)d_in[14];
    float* out = (float*)d_out;

    int B = in_sizes[0] / 18;
    int threads = 256;
    int blocks = (B + threads - 1) / threads;
    rec_policy_kernel<<<blocks, threads>>>(x, Wih_up, Whh_up, bih_up, bhh_up,
                                           W1, b1, W2, b2,
                                           Wih_dn, Whh_dn, bih_dn, bhh_dn,
                                           Wo, bo, out, B);
}

// round 4
// speedup vs baseline: 2.9829x; 1.0520x over previous
#include <cuda_runtime.h>

#define HDIM 4
#define TSTEPS 7

__device__ __forceinline__ float htanh(float x) {
    float r;
    asm("tanh.approx.f32 %0, %1;" : "=f"(r) : "f"(x));
    return r;
}

__global__ __launch_bounds__(256, 3)
void rec_policy_kernel(const float* __restrict__ x,
                       const float* __restrict__ Wih_up, const float* __restrict__ Whh_up,
                       const float* __restrict__ bih_up, const float* __restrict__ bhh_up,
                       const float* __restrict__ W1,     const float* __restrict__ b1,
                       const float* __restrict__ W2,     const float* __restrict__ b2,
                       const float* __restrict__ Wih_dn, const float* __restrict__ Whh_dn,
                       const float* __restrict__ bih_dn, const float* __restrict__ bhh_dn,
                       const float* __restrict__ Wo,     const float* __restrict__ bo,
                       float* __restrict__ out, int B)
{
    // h_up history in shared, transposed: [t*4+k][lane] -> stride-1, conflict-free
    __shared__ float hup_s[TSTEPS * HDIM][256];

    int tid = threadIdx.x;
    int row = blockIdx.x * blockDim.x + tid;
    if (row >= B) return;

    // ---- load this row: 18 floats, 8B-aligned -> 9x float2 ----
    float xr[18];
    const float2* xp = reinterpret_cast<const float2*>(x + (size_t)row * 18);
    #pragma unroll
    for (int k = 0; k < 9; k++) {
        float2 v = xp[k];
        xr[2*k]   = v.x;
        xr[2*k+1] = v.y;
    }
    const float* obs = xr;       // x[:, 0:4]
    const float* jj  = xr + 4;   // x[:, 4:11]
    const float* jjd = xr + 11;  // x[:, 11:18]

    float h[HDIM];

    // ================= UP PHASE =================
    {
        // up weights: 8 + 16 + 4 = 28 floats, all float4 loads (broadcast, L1-hit)
        float4 wiu01 = reinterpret_cast<const float4*>(Wih_up)[0]; // w[0][0],w[0][1],w[1][0],w[1][1]
        float4 wiu23 = reinterpret_cast<const float4*>(Wih_up)[1];
        float4 whu[HDIM];
        #pragma unroll
        for (int i = 0; i < HDIM; i++) whu[i] = reinterpret_cast<const float4*>(Whh_up)[i];
        float4 bi = reinterpret_cast<const float4*>(bih_up)[0];
        float4 bh = reinterpret_cast<const float4*>(bhh_up)[0];
        float bu[HDIM] = {bi.x + bh.x, bi.y + bh.y, bi.z + bh.z, bi.w + bh.w};
        float wi0[HDIM] = {wiu01.x, wiu01.z, wiu23.x, wiu23.z};
        float wi1[HDIM] = {wiu01.y, wiu01.w, wiu23.y, wiu23.w};

        #pragma unroll
        for (int i = 0; i < HDIM; i++) h[i] = 0.f;

        #pragma unroll
        for (int s = 0; s < TSTEPS; s++) {
            const int ti = TSTEPS - 1 - s;
            float pre[HDIM];
            #pragma unroll
            for (int i = 0; i < HDIM; i++) {
                float p = bu[i];
                p = fmaf(wi0[i], jj[ti],  p);
                p = fmaf(wi1[i], jjd[ti], p);
                p = fmaf(whu[i].x, h[0], p);
                p = fmaf(whu[i].y, h[1], p);
                p = fmaf(whu[i].z, h[2], p);
                p = fmaf(whu[i].w, h[3], p);
                pre[i] = p;
            }
            #pragma unroll
            for (int i = 0; i < HDIM; i++) {
                h[i] = htanh(pre[i]);
                hup_s[ti*HDIM + i][tid] = h[i];
            }
        }
    }
    // h == h_last

    // ================= MLP PHASE (stream once-used weights) =================
    {
        float z[8];
        #pragma unroll
        for (int k = 0; k < 4; k++) { z[k] = obs[k]; z[4+k] = h[k]; }

        float4 c1 = reinterpret_cast<const float4*>(b1)[0];
        float cb1[HDIM] = {c1.x, c1.y, c1.z, c1.w};
        float h0[HDIM];
        #pragma unroll
        for (int i = 0; i < HDIM; i++) {
            float4 a = reinterpret_cast<const float4*>(W1)[2*i];
            float4 b = reinterpret_cast<const float4*>(W1)[2*i+1];
            float p = cb1[i];
            p = fmaf(a.x, z[0], p); p = fmaf(a.y, z[1], p);
            p = fmaf(a.z, z[2], p); p = fmaf(a.w, z[3], p);
            p = fmaf(b.x, z[4], p); p = fmaf(b.y, z[5], p);
            p = fmaf(b.z, z[6], p); p = fmaf(b.w, z[7], p);
            h0[i] = htanh(p);
        }

        float4 c2 = reinterpret_cast<const float4*>(b2)[0];
        float cb2[HDIM] = {c2.x, c2.y, c2.z, c2.w};
        #pragma unroll
        for (int i = 0; i < HDIM; i++) {
            float4 a = reinterpret_cast<const float4*>(W2)[i];
            float p = cb2[i];
            p = fmaf(a.x, h0[0], p); p = fmaf(a.y, h0[1], p);
            p = fmaf(a.z, h0[2], p); p = fmaf(a.w, h0[3], p);
            h[i] = htanh(p);
        }
    }

    // ================= DOWN PHASE =================
    {
        float4 wid[HDIM], whd[HDIM];
        #pragma unroll
        for (int i = 0; i < HDIM; i++) {
            wid[i] = reinterpret_cast<const float4*>(Wih_dn)[i];
            whd[i] = reinterpret_cast<const float4*>(Whh_dn)[i];
        }
        float4 bi = reinterpret_cast<const float4*>(bih_dn)[0];
        float4 bh = reinterpret_cast<const float4*>(bhh_dn)[0];
        float bd[HDIM] = {bi.x + bh.x, bi.y + bh.y, bi.z + bh.z, bi.w + bh.w};
        float4 wo4 = reinterpret_cast<const float4*>(Wo)[0];
        float wo_j = Wo[4];
        float bo0  = bo[0];

        float* op = out + (size_t)row * TSTEPS;

        #pragma unroll
        for (int t = 0; t < TSTEPS; t++) {
            float a = fmaf(wo_j, jj[t], bo0);
            a = fmaf(wo4.x, h[0], a);
            a = fmaf(wo4.y, h[1], a);
            a = fmaf(wo4.z, h[2], a);
            a = fmaf(wo4.w, h[3], a);
            op[t] = a;

            float hu0 = hup_s[t*HDIM + 0][tid];
            float hu1 = hup_s[t*HDIM + 1][tid];
            float hu2 = hup_s[t*HDIM + 2][tid];
            float hu3 = hup_s[t*HDIM + 3][tid];

            float hn[HDIM];
            #pragma unroll
            for (int i = 0; i < HDIM; i++) {
                float p = bd[i];
                p = fmaf(wid[i].x, hu0, p);
                p = fmaf(wid[i].y, hu1, p);
                p = fmaf(wid[i].z, hu2, p);
                p = fmaf(wid[i].w, hu3, p);
                p = fmaf(whd[i].x, h[0], p);
                p = fmaf(whd[i].y, h[1], p);
                p = fmaf(whd[i].z, h[2], p);
                p = fmaf(whd[i].w, h[3], p);
                hn[i] = htanh(p);
            }
            #pragma unroll
            for (int i = 0; i < HDIM; i++) h[i] = hn[i];
        }
    }
}

extern "C" void kernel_launch(void* const* d_in, const int* in_sizes, int n_in,
                              void* d_out, int out_size)
{
    const float* x      = (const float*)d_in[0];
    const float* Wih_up = (const float*)d_in[1];
    const float* Whh_up = (const float*)d_in[2];
    const float* bih_up = (const float*)d_in[3];
    const float* bhh_up = (const float*)d_in[4];
    const float* W1     = (const float*)d_in[5];
    const float* b1     = (const float*)d_in[6];
    const float* W2     = (const float*)d_in[7];
    const float* b2     = (const float*)d_in[8];
    const float* Wih_dn = (const float*)d_in[9];
    const float* Whh_dn = (const float*)d_in[10];
    const float* bih_dn = (const float*)d_in[11];
    const float* bhh_dn = (const float*)d_in[12];
    const float* Wo     = (const float*)d_in[13];
    const float* bo     = (const float*)d_in[14];
    float* out = (float*)d_out;

    int B = in_sizes[0] / 18;
    int threads = 256;
    int blocks = (B + threads - 1) / threads;
    rec_policy_kernel<<<blocks, threads>>>(x, Wih_up, Whh_up, bih_up, bhh_up,
                                           W1, b1, W2, b2,
                                           Wih_dn, Whh_dn, bih_dn, bhh_dn,
                                           Wo, bo, out, B);
}